// round 17
// baseline (speedup 1.0000x reference)
#include <cuda_runtime.h>
#include <cuda_bf16.h>
#include <math.h>

#define EPS 1e-9f

static constexpr int BMAX = 1024;
static constexpr int DMAX = 512;
static constexpr int UMAX = 512;

typedef unsigned long long ull;

// Scratch (device globals). d-pair-major layouts, consumed as ulonglong2:
__device__ float4 g_LN4[BMAX * DMAX / 2];        // {l0, l1, nmf0, nmf1} per (b, d-pair)
__device__ float4 g_P4 [DMAX / 2 * UMAX / 2];    // {p(d0,u0), p(d1,u0), p(d0,u1), p(d1,u1)}
__device__ float4 g_W4 [DMAX / 2 * UMAX / 2];    // same layout for w
__device__ float4 g_DW4[DMAX / 2 * UMAX / 2];    // same layout: odd(p) ? -2w : 0

// ---------------- f32x2 helpers (R12-proven single-instr asm form) ----------------
__device__ __forceinline__ void unpack2(ull p, float& a, float& b) {
    asm("mov.b64 {%0, %1}, %2;" : "=f"(a), "=f"(b) : "l"(p));
}
__device__ __forceinline__ ull pack2(float a, float b) {
    ull r; asm("mov.b64 %0, {%1, %2};" : "=l"(r) : "f"(a), "f"(b)); return r;
}
__device__ __forceinline__ ull mul2(ull a, ull b) {
    ull r; asm("mul.rn.f32x2 %0, %1, %2;" : "=l"(r) : "l"(a), "l"(b)); return r;
}
__device__ __forceinline__ ull add2(ull a, ull b) {
    ull r; asm("add.rn.f32x2 %0, %1, %2;" : "=l"(r) : "l"(a), "l"(b)); return r;
}
__device__ __forceinline__ ull fma2(ull a, ull b, ull c) {
    ull r; asm("fma.rn.f32x2 %0, %1, %2, %3;" : "=l"(r) : "l"(a), "l"(b), "l"(c)); return r;
}
__device__ __forceinline__ float ex2(float x) {
    float r; asm("ex2.approx.f32 %0, %1;" : "=f"(r) : "f"(x)); return r;
}

// ---------------- Fused prepass (also inits out = bias) ----------------
__global__ void prep_kernel(const float* __restrict__ x,
                            const float* __restrict__ w,
                            const float* __restrict__ p,
                            const float* __restrict__ bias,
                            float* __restrict__ out,
                            int nLN4, int nPW, int nOut, int D, int U) {
    int i = blockIdx.x * blockDim.x + threadIdx.x;
    const int D2 = D >> 1, U2 = U >> 1;
    if (i < nLN4) {                       // i = b * D2 + dp
        int b  = i / D2;
        int dp = i - b * D2;
        float xe0 = x[b * D + 2 * dp]     + EPS;
        float xe1 = x[b * D + 2 * dp + 1] + EPS;
        float4 v;
        v.x = log2f(fabsf(xe0));
        v.y = log2f(fabsf(xe1));
        v.z = (xe0 < 0.f) ? 1.f : 0.f;
        v.w = (xe1 < 0.f) ? 1.f : 0.f;
        g_LN4[i] = v;
    }
    if (i < nPW) {                        // i = dp * U2 + up
        int dp = i / U2;
        int up = i - dp * U2;
        int base = (2 * dp) * U + 2 * up;
        float p00 = p[base],     p01 = p[base + 1];
        float p10 = p[base + U], p11 = p[base + U + 1];
        float w00 = w[base],     w01 = w[base + 1];
        float w10 = w[base + U], w11 = w[base + U + 1];
        g_P4[i] = make_float4(p00, p10, p01, p11);   // {d0u0, d1u0, d0u1, d1u1}
        g_W4[i] = make_float4(w00, w10, w01, w11);
        float dw00 = (fmodf(p00, 2.f) != 0.f) ? -2.f * w00 : 0.f;
        float dw10 = (fmodf(p10, 2.f) != 0.f) ? -2.f * w10 : 0.f;
        float dw01 = (fmodf(p01, 2.f) != 0.f) ? -2.f * w01 : 0.f;
        float dw11 = (fmodf(p11, 2.f) != 0.f) ? -2.f * w11 : 0.f;
        g_DW4[i] = make_float4(dw00, dw10, dw01, dw11);
    }
    if (i < nOut) out[i] = bias[i % U];
}

// ---------------- u-block paths ----------------
// MUFU path (2 elems): e = p.*l ; v = 2^e via 2x MUFU ; ws = nm.*dw + w ; acc += ws.*v
__device__ __forceinline__ void ublock_mufu(ull p, ull lp, ull nm, ull dw, ull w, ull& acc) {
    ull e = mul2(p, lp);
    float e0, e1; unpack2(e, e0, e1);
    ull v  = pack2(ex2(e0), ex2(e1));
    ull ws = fma2(nm, dw, w);
    acc = fma2(ws, v, acc);
}

// Poly path (2 elems, no MUFU): magic-number exp2 on the FMA pipe.
//   z = rn(p*l + 1.5*2^23)  -> n = z - C (exact), f = fma(p,l,-n) in [-0.5,0.5]
//   g = deg-4 Taylor 2^f;  v_bits = g_bits + (z_bits << 23)  (= g * 2^n)
__device__ __forceinline__ void ublock_poly(ull p, ull lp, ull nm, ull dw, ull w, ull& acc,
                                            ull C2, ull mC2,
                                            ull k4, ull k3, ull k2, ull k1, ull k0) {
    ull z  = fma2(p, lp, C2);
    ull t  = add2(z, mC2);                      // n as float (exact, Sterbenz)
    ull tn = t ^ 0x8000000080000000ull;         // -n (2x LOP3 imm)
    ull f  = fma2(p, lp, tn);                   // f in [-0.5, 0.5]
    ull g  = fma2(k4, f, k3);
    g = fma2(g, f, k2);
    g = fma2(g, f, k1);
    g = fma2(g, f, k0);                         // ~2^f
    // scale by 2^n: add n<<23 to each half (low mantissa bits of z hold n + 2^22;
    // (z_half << 23) == n << 23 mod 2^32)
    unsigned zl = (unsigned)z, zh = (unsigned)(z >> 32);
    unsigned gl = (unsigned)g, gh = (unsigned)(g >> 32);
    gl += zl << 23;                             // LEA
    gh += zh << 23;                             // LEA
    ull v = ((ull)gh << 32) | (ull)gl;          // register-pair reassembly
    ull ws = fma2(nm, dw, w);
    acc = fma2(ws, v, acc);
}

// ---------------- Main kernel (compile-time shapes, fully unrolled, hybrid) ----------------
static constexpr int TBT     = 4;
static constexpr int THREADS = 128;
static constexpr int DSPLIT  = 8;

template <int D, int U>
__global__ __launch_bounds__(THREADS, 7)
void power_layer_kernel(float* __restrict__ out) {
    constexpr int U2  = U / 2;        // 256 u-pairs
    constexpr int D2  = D / 2;        // 256 d-pairs
    constexpr int nDP = D2 / DSPLIT;  // 32 d-pairs per block

    const int up  = blockIdx.y * THREADS + threadIdx.x;   // u-pair index
    const int b0  = blockIdx.x * TBT;
    const int dp0 = blockIdx.z * nDP;

    const ulonglong2* __restrict__ Pp  = (const ulonglong2*)(g_P4  + dp0 * U2 + up);
    const ulonglong2* __restrict__ Wp  = (const ulonglong2*)(g_W4  + dp0 * U2 + up);
    const ulonglong2* __restrict__ DWp = (const ulonglong2*)(g_DW4 + dp0 * U2 + up);
    const ulonglong2* __restrict__ LNp = (const ulonglong2*)(g_LN4 + (size_t)b0 * D2 + dp0);

    // Packed constants for the poly path (exp2 Taylor deg-4 + magic number)
    const ull C2  = pack2(12582912.0f, 12582912.0f);     // 1.5 * 2^23
    const ull mC2 = pack2(-12582912.0f, -12582912.0f);
    const ull k0  = pack2(1.0f,            1.0f);
    const ull k1  = pack2(0.69314718056f,  0.69314718056f);
    const ull k2  = pack2(0.24022650696f,  0.24022650696f);
    const ull k3  = pack2(0.05550410866f,  0.05550410866f);
    const ull k4  = pack2(0.00961812911f,  0.00961812911f);

    ull acc[TBT][2];
#pragma unroll
    for (int bb = 0; bb < TBT; bb++) { acc[bb][0] = 0ull; acc[bb][1] = 0ull; }

#pragma unroll
    for (int j = 0; j < nDP; j++) {
        const ulonglong2 P  = Pp [j * U2];   // .x = {p(d0,u0),p(d1,u0)}, .y = u1
        const ulonglong2 W  = Wp [j * U2];
        const ulonglong2 DW = DWp[j * U2];

#pragma unroll
        for (int bb = 0; bb < TBT; bb++) {
            const ulonglong2 L = LNp[bb * D2 + j];   // .x = {l0,l1}, .y = {nmf0,nmf1}

            // u-block index k = bb*2 + u; poly path for k in {1,4,7} (3/8 of work)
            constexpr int POLY_MASK = (1 << 1) | (1 << 4) | (1 << 7);
            const int k0i = bb * 2;

            if ((POLY_MASK >> k0i) & 1)
                ublock_poly(P.x, L.x, L.y, DW.x, W.x, acc[bb][0],
                            C2, mC2, k4, k3, k2, k1, k0);
            else
                ublock_mufu(P.x, L.x, L.y, DW.x, W.x, acc[bb][0]);

            if ((POLY_MASK >> (k0i + 1)) & 1)
                ublock_poly(P.y, L.x, L.y, DW.y, W.y, acc[bb][1],
                            C2, mC2, k4, k3, k2, k1, k0);
            else
                ublock_mufu(P.y, L.x, L.y, DW.y, W.y, acc[bb][1]);
        }
    }

    float* o = out + (size_t)b0 * U + 2 * up;
#pragma unroll
    for (int bb = 0; bb < TBT; bb++) {
        float a0, a1;
        unpack2(acc[bb][0], a0, a1);
        atomicAdd(o + bb * U, a0 + a1);
        unpack2(acc[bb][1], a0, a1);
        atomicAdd(o + bb * U + 1, a0 + a1);
    }
}

// ---------------- Generic fallback (only if shapes differ) ----------------
__global__ void fallback_kernel(const float* __restrict__ x,
                                const float* __restrict__ w,
                                const float* __restrict__ p,
                                const float* __restrict__ bias,
                                float* __restrict__ out,
                                int B, int D, int U) {
    int i = blockIdx.x * blockDim.x + threadIdx.x;
    if (i >= B * U) return;
    int b = i / U, u = i % U;
    float s = 0.f;
    for (int d = 0; d < D; d++) {
        float xe = x[b * D + d] + EPS;
        float pv = p[d * U + u];
        float ap = powf(fabsf(xe), pv);
        bool odd = (fmodf(pv, 2.f) != 0.f);
        float sv = (odd && xe < 0.f) ? -ap : ap;
        s += w[d * U + u] * sv;
    }
    out[i] = s + bias[u];
}

// ---------------- Launch ----------------
extern "C" void kernel_launch(void* const* d_in, const int* in_sizes, int n_in,
                              void* d_out, int out_size) {
    const float* x    = (const float*)d_in[0];
    const float* w    = (const float*)d_in[1];
    const float* p    = (const float*)d_in[2];
    const float* bias = (const float*)d_in[3];
    float* out        = (float*)d_out;

    const int U = in_sizes[3];            // 512
    const int D = in_sizes[1] / U;        // 512
    const int B = in_sizes[0] / D;        // 1024

    if (U == 512 && D == 512 && B == 1024) {
        const int nLN4 = B * D / 2;          // 262144
        const int nPW  = (D / 2) * (U / 2);  // 65536
        const int nOut = out_size;           // 524288
        int nmax = nLN4 > nPW ? nLN4 : nPW;
        if (nOut > nmax) nmax = nOut;
        prep_kernel<<<(nmax + 255) / 256, 256>>>(x, w, p, bias, out,
                                                 nLN4, nPW, nOut, D, U);

        // grid: (B/TBT, U2/THREADS, DSPLIT) = (256, 2, 8) = 4096 blocks
        dim3 grid(B / TBT, (U / 2) / THREADS, DSPLIT);
        power_layer_kernel<512, 512><<<grid, THREADS>>>(out);
    } else {
        int n = B * U;
        fallback_kernel<<<(n + 255) / 256, 256>>>(x, w, p, bias, out, B, D, U);
    }
}